// round 1
// baseline (speedup 1.0000x reference)
#include <cuda_runtime.h>
#include <math.h>

#define Bn 256
#define Tn 250
#define Zn 128
#define Hn 256
#define Dn 512
#define Kn 20
#define Pn 123   // 6K+3

// ------------------- scratch (static device globals; allocation-free) -----
__device__ float g_hf[2][Bn*Hn];
__device__ float g_cf[Bn*Hn];
__device__ float g_hb[2][Bn*Hn];
__device__ float g_cb[Bn*Hn];
__device__ float g_z [Bn*Zn];
__device__ float g_zg[Bn*4*Dn];
__device__ float g_hd[2][Bn*Dn];
__device__ float g_cd[Bn*Dn];
__device__ float g_hs[(size_t)Tn*Bn*Dn];   // decoder hidden states (t, b, d)

__device__ __forceinline__ float sigf(float x) { return 1.0f / (1.0f + expf(-x)); }

// ------------------- init: zero initial h/c for encoder -------------------
__global__ void init_kernel() {
    int i = blockIdx.x * blockDim.x + threadIdx.x;
    if (i < Bn * Hn) {
        g_hf[0][i] = 0.f; g_cf[i] = 0.f;
        g_hb[0][i] = 0.f; g_cb[i] = 0.f;
    }
}

// ------------------- encoder LSTM step (both directions) ------------------
// CTA: 32 batch rows x 16 hidden units (64 gate columns gathered from the
// four gate blocks). Fuses x@Wx + bias + h@Wh + gate nonlin + c/h update.
__global__ __launch_bounds__(256) void enc_step(
    const float* __restrict__ data,
    const float* __restrict__ Wx_f, const float* __restrict__ Wh_f, const float* __restrict__ b_f,
    const float* __restrict__ Wx_b, const float* __restrict__ Wh_b, const float* __restrict__ b_b,
    int t)
{
    const int dir = blockIdx.z;
    const float* __restrict__ Wx  = dir ? Wx_b : Wx_f;
    const float* __restrict__ Wh  = dir ? Wh_b : Wh_f;
    const float* __restrict__ bb  = dir ? b_b  : b_f;
    const float* __restrict__ hin = dir ? g_hb[t & 1] : g_hf[t & 1];
    float* __restrict__ hout      = dir ? g_hb[(t + 1) & 1] : g_hf[(t + 1) & 1];
    float* __restrict__ cst       = dir ? g_cb : g_cf;
    const int xtime = dir ? (Tn - t) : (t + 1);   // enc_in index (+1 time offset)

    __shared__ float As[32][33];     // [k][row], padded
    __shared__ float Ws[32][64];     // [k][gatecol]
    __shared__ float Wxs[5][64];
    __shared__ float bs[64];

    const int tid = threadIdx.x;
    const int tx = tid & 15;         // unit within tile
    const int ty = tid >> 4;         // row group (2 rows each)
    const int b0 = blockIdx.x * 32;
    const int u0 = blockIdx.y * 16;

    for (int i = tid; i < 5 * 64; i += 256) {
        int f = i >> 6, c = i & 63;
        Wxs[f][c] = Wx[f * (4 * Hn) + (c >> 4) * Hn + u0 + (c & 15)];
    }
    if (tid < 64) bs[tid] = bb[(tid >> 4) * Hn + u0 + (tid & 15)];

    float acc[2][4] = {};

    for (int k0 = 0; k0 < Hn; k0 += 32) {
        __syncthreads();
        {   // A tile: 32 rows x 32 k, stored transposed
            int row = tid >> 3, k4 = tid & 7;
            float4 v = *(const float4*)&hin[(b0 + row) * Hn + k0 + k4 * 4];
            As[k4 * 4 + 0][row] = v.x; As[k4 * 4 + 1][row] = v.y;
            As[k4 * 4 + 2][row] = v.z; As[k4 * 4 + 3][row] = v.w;
        }
        #pragma unroll
        for (int i = 0; i < 2; i++) {   // W tile: 32 k x (4 gates x 16 units)
            int fi = tid + i * 256;
            int k = fi >> 4, rem = fi & 15;
            float4 v = *(const float4*)&Wh[(k0 + k) * (4 * Hn) + (rem >> 2) * Hn + u0 + (rem & 3) * 4];
            float* wp = &Ws[k][(rem >> 2) * 16 + (rem & 3) * 4];
            wp[0] = v.x; wp[1] = v.y; wp[2] = v.z; wp[3] = v.w;
        }
        __syncthreads();
        #pragma unroll
        for (int k = 0; k < 32; k++) {
            float a0 = As[k][ty * 2 + 0], a1 = As[k][ty * 2 + 1];
            float w0 = Ws[k][tx], w1 = Ws[k][16 + tx], w2 = Ws[k][32 + tx], w3 = Ws[k][48 + tx];
            acc[0][0] = fmaf(a0, w0, acc[0][0]); acc[0][1] = fmaf(a0, w1, acc[0][1]);
            acc[0][2] = fmaf(a0, w2, acc[0][2]); acc[0][3] = fmaf(a0, w3, acc[0][3]);
            acc[1][0] = fmaf(a1, w0, acc[1][0]); acc[1][1] = fmaf(a1, w1, acc[1][1]);
            acc[1][2] = fmaf(a1, w2, acc[1][2]); acc[1][3] = fmaf(a1, w3, acc[1][3]);
        }
    }

    const int u = u0 + tx;
    #pragma unroll
    for (int r = 0; r < 2; r++) {
        int b = b0 + ty * 2 + r;
        const float* x = &data[((size_t)b * (Tn + 1) + xtime) * 5];
        float x0 = x[0], x1 = x[1], x2 = x[2], x3 = x[3], x4 = x[4];
        float p[4];
        #pragma unroll
        for (int g = 0; g < 4; g++) {
            float s = acc[r][g] + bs[g * 16 + tx];
            s = fmaf(x0, Wxs[0][g * 16 + tx], s);
            s = fmaf(x1, Wxs[1][g * 16 + tx], s);
            s = fmaf(x2, Wxs[2][g * 16 + tx], s);
            s = fmaf(x3, Wxs[3][g * 16 + tx], s);
            s = fmaf(x4, Wxs[4][g * 16 + tx], s);
            p[g] = s;
        }
        float co = cst[b * Hn + u];
        float c  = sigf(p[1]) * co + sigf(p[0]) * tanhf(p[2]);
        float h  = sigf(p[3]) * tanhf(c);
        cst[b * Hn + u]  = c;
        hout[b * Hn + u] = h;
    }
}

// ------------------- latent stage 1: z_mean / z_logvar / z ----------------
__global__ void latent1(const float* __restrict__ W, const float* __restrict__ bias,
                        const float* __restrict__ eps,
                        float* __restrict__ zm, float* __restrict__ zl)
{
    int b = blockIdx.x, j = threadIdx.x;   // 128 threads
    const float* hf = &g_hf[0][b * Hn];    // final parity: T even -> buffer 0
    const float* hb = &g_hb[0][b * Hn];
    float sm = bias[j], sl = bias[j + Zn];
    for (int k = 0; k < Hn; k++) {
        float a = hf[k];
        sm = fmaf(a, W[k * (2 * Zn) + j], sm);
        sl = fmaf(a, W[k * (2 * Zn) + Zn + j], sl);
    }
    for (int k = 0; k < Hn; k++) {
        float a = hb[k];
        sm = fmaf(a, W[(Hn + k) * (2 * Zn) + j], sm);
        sl = fmaf(a, W[(Hn + k) * (2 * Zn) + Zn + j], sl);
    }
    zm[b * Zn + j] = sm;
    zl[b * Zn + j] = sl;
    g_z[b * Zn + j] = sm + expf(0.5f * sl) * eps[b * Zn + j];
}

// ------------------- latent stage 2: h0/c0 and zg --------------------------
__global__ void latent2(const float* __restrict__ init_W, const float* __restrict__ init_b,
                        const float* __restrict__ dec_Wx, const float* __restrict__ dec_b)
{
    int b = blockIdx.x;
    int col = blockIdx.y * 256 + threadIdx.x;   // 0..3071
    __shared__ float zs[Zn];
    if (threadIdx.x < Zn) zs[threadIdx.x] = g_z[b * Zn + threadIdx.x];
    __syncthreads();
    if (col < 2 * Dn) {
        float s = init_b[col];
        for (int k = 0; k < Zn; k++) s = fmaf(zs[k], init_W[k * (2 * Dn) + col], s);
        s = tanhf(s);
        if (col < Dn) g_hd[0][b * Dn + col] = s;
        else          g_cd[b * Dn + (col - Dn)] = s;
    } else {
        int c2 = col - 2 * Dn;   // 0..2047
        float s = dec_b[c2];
        for (int k = 0; k < Zn; k++) s = fmaf(zs[k], dec_Wx[(5 + k) * (4 * Dn) + c2], s);
        g_zg[b * (4 * Dn) + c2] = s;
    }
}

// ------------------- decoder LSTM step ------------------------------------
__global__ __launch_bounds__(256) void dec_step(
    const float* __restrict__ data,
    const float* __restrict__ dec_Wx, const float* __restrict__ Wh, int t)
{
    const float* __restrict__ hin = g_hd[t & 1];
    float* __restrict__ hout      = g_hd[(t + 1) & 1];

    __shared__ float As[32][33];
    __shared__ float Ws[32][64];
    __shared__ float Wxs[5][64];

    const int tid = threadIdx.x;
    const int tx = tid & 15;
    const int ty = tid >> 4;
    const int b0 = blockIdx.x * 32;
    const int u0 = blockIdx.y * 16;

    for (int i = tid; i < 5 * 64; i += 256) {
        int f = i >> 6, c = i & 63;
        Wxs[f][c] = dec_Wx[f * (4 * Dn) + (c >> 4) * Dn + u0 + (c & 15)];
    }

    float acc[2][4] = {};

    for (int k0 = 0; k0 < Dn; k0 += 32) {
        __syncthreads();
        {
            int row = tid >> 3, k4 = tid & 7;
            float4 v = *(const float4*)&hin[(b0 + row) * Dn + k0 + k4 * 4];
            As[k4 * 4 + 0][row] = v.x; As[k4 * 4 + 1][row] = v.y;
            As[k4 * 4 + 2][row] = v.z; As[k4 * 4 + 3][row] = v.w;
        }
        #pragma unroll
        for (int i = 0; i < 2; i++) {
            int fi = tid + i * 256;
            int k = fi >> 4, rem = fi & 15;
            float4 v = *(const float4*)&Wh[(k0 + k) * (4 * Dn) + (rem >> 2) * Dn + u0 + (rem & 3) * 4];
            float* wp = &Ws[k][(rem >> 2) * 16 + (rem & 3) * 4];
            wp[0] = v.x; wp[1] = v.y; wp[2] = v.z; wp[3] = v.w;
        }
        __syncthreads();
        #pragma unroll
        for (int k = 0; k < 32; k++) {
            float a0 = As[k][ty * 2 + 0], a1 = As[k][ty * 2 + 1];
            float w0 = Ws[k][tx], w1 = Ws[k][16 + tx], w2 = Ws[k][32 + tx], w3 = Ws[k][48 + tx];
            acc[0][0] = fmaf(a0, w0, acc[0][0]); acc[0][1] = fmaf(a0, w1, acc[0][1]);
            acc[0][2] = fmaf(a0, w2, acc[0][2]); acc[0][3] = fmaf(a0, w3, acc[0][3]);
            acc[1][0] = fmaf(a1, w0, acc[1][0]); acc[1][1] = fmaf(a1, w1, acc[1][1]);
            acc[1][2] = fmaf(a1, w2, acc[1][2]); acc[1][3] = fmaf(a1, w3, acc[1][3]);
        }
    }

    const int u = u0 + tx;
    #pragma unroll
    for (int r = 0; r < 2; r++) {
        int b = b0 + ty * 2 + r;
        const float* x = &data[((size_t)b * (Tn + 1) + t) * 5];   // dec_in = data[:, :T]
        float x0 = x[0], x1 = x[1], x2 = x[2], x3 = x[3], x4 = x[4];
        float p[4];
        #pragma unroll
        for (int g = 0; g < 4; g++) {
            float s = acc[r][g] + g_zg[b * (4 * Dn) + g * Dn + u];
            s = fmaf(x0, Wxs[0][g * 16 + tx], s);
            s = fmaf(x1, Wxs[1][g * 16 + tx], s);
            s = fmaf(x2, Wxs[2][g * 16 + tx], s);
            s = fmaf(x3, Wxs[3][g * 16 + tx], s);
            s = fmaf(x4, Wxs[4][g * 16 + tx], s);
            p[g] = s;
        }
        float co = g_cd[b * Dn + u];
        float c  = sigf(p[1]) * co + sigf(p[0]) * tanhf(p[2]);
        float h  = sigf(p[3]) * tanhf(c);
        g_cd[b * Dn + u]  = c;
        hout[b * Dn + u]  = h;
        g_hs[((size_t)t * Bn + b) * Dn + u] = h;
    }
}

// ------------------- output head: hs @ mix_W + softmax/transforms ---------
__global__ __launch_bounds__(256) void mix_kernel(
    const float* __restrict__ Wm, const float* __restrict__ bm, float* __restrict__ out)
{
    __shared__ float As[32][33];
    __shared__ float Ws[32][128];
    __shared__ float ys[32 * 129];
    const int tid = threadIdx.x;
    const int tx = tid & 31, ty = tid >> 5;
    const int row0 = blockIdx.x * 32;
    float acc[4][4] = {};

    for (int k0 = 0; k0 < Dn; k0 += 32) {
        __syncthreads();
        for (int i = tid; i < 32 * 32; i += 256) {
            int r = i >> 5, k = i & 31;
            As[k][r] = g_hs[((size_t)(row0 + r)) * Dn + k0 + k];
        }
        for (int i = tid; i < 32 * 128; i += 256) {
            int k = i >> 7, c = i & 127;
            Ws[k][c] = (c < Pn) ? Wm[(k0 + k) * Pn + c] : 0.f;
        }
        __syncthreads();
        #pragma unroll
        for (int k = 0; k < 32; k++) {
            float a0 = As[k][ty * 4 + 0], a1 = As[k][ty * 4 + 1];
            float a2 = As[k][ty * 4 + 2], a3 = As[k][ty * 4 + 3];
            float4 w = *(const float4*)&Ws[k][tx * 4];
            acc[0][0] = fmaf(a0, w.x, acc[0][0]); acc[0][1] = fmaf(a0, w.y, acc[0][1]);
            acc[0][2] = fmaf(a0, w.z, acc[0][2]); acc[0][3] = fmaf(a0, w.w, acc[0][3]);
            acc[1][0] = fmaf(a1, w.x, acc[1][0]); acc[1][1] = fmaf(a1, w.y, acc[1][1]);
            acc[1][2] = fmaf(a1, w.z, acc[1][2]); acc[1][3] = fmaf(a1, w.w, acc[1][3]);
            acc[2][0] = fmaf(a2, w.x, acc[2][0]); acc[2][1] = fmaf(a2, w.y, acc[2][1]);
            acc[2][2] = fmaf(a2, w.z, acc[2][2]); acc[2][3] = fmaf(a2, w.w, acc[2][3]);
            acc[3][0] = fmaf(a3, w.x, acc[3][0]); acc[3][1] = fmaf(a3, w.y, acc[3][1]);
            acc[3][2] = fmaf(a3, w.z, acc[3][2]); acc[3][3] = fmaf(a3, w.w, acc[3][3]);
        }
    }

    #pragma unroll
    for (int r = 0; r < 4; r++)
        #pragma unroll
        for (int c = 0; c < 4; c++) {
            int cc = tx * 4 + c;
            float v = acc[r][c] + ((cc < Pn) ? bm[cc] : 0.f);
            ys[(ty * 4 + r) * 129 + cc] = v;
        }
    __syncthreads();

    if (tid < 32) {
        int row = row0 + tid;          // = t*Bn + b
        int tt = row >> 8;             // / Bn
        int bb2 = row & 255;
        float* o = out + ((size_t)bb2 * Tn + tt) * Pn;
        const float* y = &ys[tid * 129];
        float m = y[0];
        #pragma unroll
        for (int j = 1; j < Kn; j++) m = fmaxf(m, y[j]);
        float e[Kn]; float s = 0.f;
        #pragma unroll
        for (int j = 0; j < Kn; j++) { e[j] = expf(y[j] - m); s += e[j]; }
        float inv = 1.f / s;
        #pragma unroll
        for (int j = 0; j < Kn; j++) o[j] = e[j] * inv;                    // pi
        #pragma unroll
        for (int j = Kn; j < 3 * Kn; j++) o[j] = y[j];                     // mu
        #pragma unroll
        for (int j = 3 * Kn; j < 5 * Kn; j++) o[j] = expf(y[j]);           // sigma
        #pragma unroll
        for (int j = 5 * Kn; j < 6 * Kn; j++) o[j] = tanhf(y[j]);          // rho
        o[120] = y[120]; o[121] = y[121]; o[122] = y[122];                 // pen
    }
}

// ------------------- launcher ----------------------------------------------
extern "C" void kernel_launch(void* const* d_in, const int* in_sizes, int n_in,
                              void* d_out, int out_size)
{
    (void)in_sizes; (void)n_in; (void)out_size;
    const float* data      = (const float*)d_in[0];
    const float* eps       = (const float*)d_in[1];
    const float* enc_Wx_f  = (const float*)d_in[2];
    const float* enc_Wh_f  = (const float*)d_in[3];
    const float* enc_b_f   = (const float*)d_in[4];
    const float* enc_Wx_b  = (const float*)d_in[5];
    const float* enc_Wh_b  = (const float*)d_in[6];
    const float* enc_b_b   = (const float*)d_in[7];
    const float* enc_out_W = (const float*)d_in[8];
    const float* enc_out_b = (const float*)d_in[9];
    const float* init_W    = (const float*)d_in[10];
    const float* init_b    = (const float*)d_in[11];
    const float* dec_Wx    = (const float*)d_in[12];
    const float* dec_Wh    = (const float*)d_in[13];
    const float* dec_b     = (const float*)d_in[14];
    const float* mix_W     = (const float*)d_in[15];
    const float* mix_b     = (const float*)d_in[16];
    float* out = (float*)d_out;

    const size_t params_sz = (size_t)Bn * Tn * Pn;

    init_kernel<<<256, 256>>>();

    dim3 eg(Bn / 32, Hn / 16, 2);
    for (int t = 0; t < Tn; t++)
        enc_step<<<eg, 256>>>(data, enc_Wx_f, enc_Wh_f, enc_b_f,
                              enc_Wx_b, enc_Wh_b, enc_b_b, t);

    latent1<<<Bn, 128>>>(enc_out_W, enc_out_b, eps,
                         out + params_sz, out + params_sz + (size_t)Bn * Zn);
    latent2<<<dim3(Bn, 12), 256>>>(init_W, init_b, dec_Wx, dec_b);

    dim3 dg(Bn / 32, Dn / 16, 1);
    for (int t = 0; t < Tn; t++)
        dec_step<<<dg, 256>>>(data, dec_Wx, dec_Wh, t);

    mix_kernel<<<(Tn * Bn) / 32, 256>>>(mix_W, mix_b, out);
}